// round 5
// baseline (speedup 1.0000x reference)
#include <cuda_runtime.h>
#include <cuda_bf16.h>
#include <cstdint>

#define DIM 4096
#define THREADS 64
#define REGS 64
#define SROW 68   // 64 + 4 pad words: conflict-free strided AND vectorized access

// In-register 64-point Walsh-Hadamard (unnormalized butterflies).
__device__ __forceinline__ void fwht64(float r[REGS]) {
#pragma unroll
    for (int h = 1; h < REGS; h <<= 1) {
#pragma unroll
        for (int k = 0; k < REGS; k++) {
            if ((k & h) == 0) {
                float a = r[k];
                float b = r[k + h];
                r[k]     = a + b;
                r[k + h] = a - b;
            }
        }
    }
}

__global__ __launch_bounds__(THREADS)
void fwht4096_kernel(const float* __restrict__ x, float* __restrict__ y) {
    __shared__ __align__(16) float s[REGS * SROW];   // 17408 B

    const int t = threadIdx.x;
    const float* xr = x + (size_t)blockIdx.x * DIM;
    float*       yr = y + (size_t)blockIdx.x * DIM;

    float r[REGS];

    // ---- Load: r[k] = x[k*64 + t]. Per warp per k: one contiguous 128B line
    // (sector-perfect). 64 independent loads -> deep MLP.
#pragma unroll
    for (int k = 0; k < REGS; k++)
        r[k] = xr[k * 64 + t];

    // ---- Phase 1: FWHT over bits 6..11 (the k index).
    fwht64(r);

    // ---- Exchange write: i = k*64 + t -> s[k*68 + t].
    // Fixed k, lanes: bank (68k + 32w + lane) % 32 = (4k + lane) % 32, distinct. CF.
#pragma unroll
    for (int k = 0; k < REGS; k++)
        s[k * SROW + t] = r[k];
    __syncthreads();

    // ---- Exchange read: thread t owns i = t*64 + c -> s[t*68 + c], contiguous.
    // Byte offset 272*t is 16B-aligned; LDS.128 banks 4(t+m) disjoint per
    // quarter-warp. Conflict-free.
    {
        const float4* s4 = reinterpret_cast<const float4*>(&s[t * SROW]);
#pragma unroll
        for (int m = 0; m < 16; m++) {
            float4 v = s4[m];
            r[4*m+0] = v.x; r[4*m+1] = v.y; r[4*m+2] = v.z; r[4*m+3] = v.w;
        }
    }

    // ---- Phase 2: FWHT over bits 0..5 (the c index).
    fwht64(r);

    // ---- Scale by 1/sqrt(4096) = 1/64 (exact).
    const float sc = 0.015625f;
#pragma unroll
    for (int c = 0; c < REGS; c++) r[c] *= sc;

    // ---- Exchange-2 write: back into the SAME row region this thread just
    // read (only thread t touches row t between the two barriers -> no
    // barrier needed before this write). 16x STS.128, conflict-free as above.
    {
        float4* s4 = reinterpret_cast<float4*>(&s[t * SROW]);
#pragma unroll
        for (int m = 0; m < 16; m++) {
            float4 v;
            v.x = r[4*m+0]; v.y = r[4*m+1]; v.z = r[4*m+2]; v.w = r[4*m+3];
            s4[m] = v;
        }
    }
    __syncthreads();

    // ---- Final: strided smem read (conflict-free, same pattern as exchange
    // write) + fully coalesced global store.
#pragma unroll
    for (int k = 0; k < REGS; k++)
        yr[k * 64 + t] = s[k * SROW + t];
}

extern "C" void kernel_launch(void* const* d_in, const int* in_sizes, int n_in,
                              void* d_out, int out_size) {
    const float* x = (const float*)d_in[0];
    float* y = (float*)d_out;
    const int n = in_sizes[0];
    const int rows = n / DIM;   // 8192
    fwht4096_kernel<<<rows, THREADS>>>(x, y);
}

// round 6
// speedup vs baseline: 1.0113x; 1.0113x over previous
#include <cuda_runtime.h>
#include <cuda_bf16.h>
#include <cstdint>

#define DIM 4096
#define THREADS 128
#define SROW 36   // padded stride (words) per 32-word group: conflict-free both patterns
#define GRID 1480 // 148 SMs x 10 resident CTAs -> single persistent wave

// In-register 32-point Walsh-Hadamard (unnormalized butterflies).
__device__ __forceinline__ void fwht32(float r[32]) {
#pragma unroll
    for (int h = 1; h < 32; h <<= 1) {
#pragma unroll
        for (int k = 0; k < 32; k++) {
            if ((k & h) == 0) {
                float a = r[k];
                float b = r[k + h];
                r[k]     = a + b;
                r[k + h] = a - b;
            }
        }
    }
}

__global__ __launch_bounds__(THREADS, 10)
void fwht4096_kernel(const float* __restrict__ x, float* __restrict__ y, int rows) {
    // Logical element i (12 bits) stored at phys(i) = (i>>5)*SROW + (i&31).
    __shared__ float s[128 * SROW];   // 18432 B

    const int t    = threadIdx.x;
    const int w    = t >> 5;
    const int lane = t & 31;

    for (int row = blockIdx.x; row < rows; row += GRID) {
        const float* xr = x + (size_t)row * DIM;
        float*       yr = y + (size_t)row * DIM;

        float r[32];

        // ---- Load: r[k] = x[k*128 + t]. Per warp per k: one contiguous 128B
        // line (sector-perfect). Issued BEFORE the WAR barrier below, so next
        // row's loads overlap previous row's smem-read/store drain.
#pragma unroll
        for (int k = 0; k < 32; k++)
            r[k] = xr[k * 128 + t];

        // ---- Phase A: butterflies over i bits 7..11 (== bits of k).
        fwht32(r);

        // ---- WAR guard: previous iteration's final strided smem reads must
        // complete in ALL threads before we overwrite s. (No-op on first row.)
        if (row != blockIdx.x) __syncthreads();

        // ---- Exchange 1 write: i = k*128 + t  ->  phys = (4k + w)*36 + lane.
        // Banks (16k + 4w + lane) mod 32: distinct per lane -> conflict-free.
#pragma unroll
        for (int k = 0; k < 32; k++)
            s[(4 * k + w) * SROW + lane] = r[k];
        __syncthreads();

        // ---- Exchange 1 read: thread t owns i = c + (t&3)*32 + (t>>2)*128,
        // c=0..31. i>>5 == t, so phys = t*36 + c : contiguous, 144B-aligned ->
        // 8x LDS.128, conflict-free (banks 4(t+m) disjoint per quarter-warp).
        {
            const float4* s4 = reinterpret_cast<const float4*>(&s[t * SROW]);
#pragma unroll
            for (int m = 0; m < 8; m++) {
                float4 v = s4[m];
                r[4*m+0] = v.x; r[4*m+1] = v.y; r[4*m+2] = v.z; r[4*m+3] = v.w;
            }
        }

        // ---- Phase B part 1: butterflies over i bits 0..4 (== bits of c).
        fwht32(r);

        // ---- Phase B part 2: bits 5,6 of i live in lane bits 0,1 -> shuffles.
        {
            const float sgn5 = (t & 1) ? -1.0f : 1.0f;
#pragma unroll
            for (int k = 0; k < 32; k++) {
                float o = __shfl_xor_sync(0xFFFFFFFFu, r[k], 1);
                r[k] = fmaf(sgn5, r[k], o);   // low: a+b, high: a-b
            }
            const float sgn6 = (t & 2) ? -1.0f : 1.0f;
#pragma unroll
            for (int k = 0; k < 32; k++) {
                float o = __shfl_xor_sync(0xFFFFFFFFu, r[k], 2);
                r[k] = fmaf(sgn6, r[k], o);
            }
        }

        // ---- Exchange 2 write: same phys range this thread just read
        // ([36t, 36t+32)) -> no barrier needed before this write. 8x STS.128.
        {
            float4* s4 = reinterpret_cast<float4*>(&s[t * SROW]);
#pragma unroll
            for (int m = 0; m < 8; m++) {
                float4 v;
                v.x = r[4*m+0]; v.y = r[4*m+1]; v.z = r[4*m+2]; v.w = r[4*m+3];
                s4[m] = v;
            }
        }
        __syncthreads();

        // ---- Exchange 2 read + scaled store: i = k*128 + t, coalesced STG.32.
        const float sc = 0.015625f;   // 1/sqrt(4096), exact
#pragma unroll
        for (int k = 0; k < 32; k++)
            yr[k * 128 + t] = s[(4 * k + w) * SROW + lane] * sc;
    }
}

extern "C" void kernel_launch(void* const* d_in, const int* in_sizes, int n_in,
                              void* d_out, int out_size) {
    const float* x = (const float*)d_in[0];
    float* y = (float*)d_out;
    const int n = in_sizes[0];
    const int rows = n / DIM;   // 8192
    const int grid = (rows < GRID) ? rows : GRID;
    fwht4096_kernel<<<grid, THREADS>>>(x, y, rows);
}